// round 1
// baseline (speedup 1.0000x reference)
#include <cuda_runtime.h>
#include <math.h>

// ---------------------------------------------------------------------------
// Problem constants
// ---------------------------------------------------------------------------
#define BATCH   256
#define DIM     384
#define KEY_DIM 32
#define HEADS   8
#define RES     14
#define NSP     196            // RES*RES
#define NH_KD   256            // KEY_DIM*HEADS
#define DV      128            // RATIO*KEY_DIM
#define DH      1024           // DV*HEADS
#define H_QKV   1536           // DH + 2*NH_KD
#define NTOT    (BATCH*NSP)    // 50176
#define EPS     1e-5f

// ---------------------------------------------------------------------------
// Scratch (device globals; allocation-free per harness rules)
// ---------------------------------------------------------------------------
__device__ float g_xT [DIM   * NTOT];   //  77 MB : x transposed  [384, 50176]
__device__ float g_qkv[H_QKV * NTOT];   // 308 MB : qkv (BN'd)    [1536, 50176]
__device__ float g_q  [NH_KD * NTOT];   //  51 MB : q after dwconv+BN
__device__ float g_o  [DH    * NTOT];   // 205 MB : relu(attn out) [1024, 50176]

// ---------------------------------------------------------------------------
// K0: transpose x [B,384,196] -> xT [384, B*196]
// ---------------------------------------------------------------------------
__global__ void k_transpose(const float* __restrict__ x, float* __restrict__ xT) {
    int i = blockIdx.x * 256 + threadIdx.x;
    if (i >= DIM * NTOT) return;
    int n = i % NSP;
    int c = (i / NSP) % DIM;
    int b = i / (NSP * DIM);
    xT[c * NTOT + b * NSP + n] = x[i];
}

// ---------------------------------------------------------------------------
// Register-tiled fp32 GEMM with fused BN epilogue.
//   C[M,N] = BN( A[M,K] * B[K,N] )
//   scatter==0 : C row-major [M,N]
//   scatter==1 : C written as out[b, r, sp] with col = b*196+sp (final layout)
// BM=128, BN=64, BK=16, 256 threads, 8x4 per thread.
// ---------------------------------------------------------------------------
#define BM 128
#define BN 64
#define BK 16
#define TM 8
#define TN 4

__global__ __launch_bounds__(256) void k_gemm_bn(
    const float* __restrict__ A, const float* __restrict__ B,
    float* __restrict__ C, int M, int N, int K,
    const float* __restrict__ gg, const float* __restrict__ bb,
    const float* __restrict__ mm, const float* __restrict__ vv,
    int scatter)
{
    __shared__ float As[BK][BM + 2];   // pad -> conflict-free transposed store
    __shared__ float Bs[BK][BN];

    const int tx = threadIdx.x & 15;
    const int ty = threadIdx.x >> 4;
    const int row0 = blockIdx.y * BM;
    const int col0 = blockIdx.x * BN;

    float acc[TM][TN];
#pragma unroll
    for (int i = 0; i < TM; i++)
#pragma unroll
        for (int j = 0; j < TN; j++) acc[i][j] = 0.f;

    for (int k0 = 0; k0 < K; k0 += BK) {
        // load A tile (BM x BK), transposed into As[k][m]
#pragma unroll
        for (int i = 0; i < (BM * BK) / 256; i++) {
            int idx = threadIdx.x + i * 256;
            int m = idx >> 4;
            int k = idx & 15;
            As[k][m] = A[(row0 + m) * K + k0 + k];
        }
        // load B tile (BK x BN)
#pragma unroll
        for (int i = 0; i < (BK * BN) / 256; i++) {
            int idx = threadIdx.x + i * 256;
            int k = idx >> 6;
            int n = idx & 63;
            Bs[k][n] = B[(k0 + k) * N + col0 + n];
        }
        __syncthreads();

#pragma unroll
        for (int kk = 0; kk < BK; kk++) {
            float a[TM];
#pragma unroll
            for (int i = 0; i < TM; i++) a[i] = As[kk][ty * TM + i];
            float4 b4 = *(const float4*)&Bs[kk][tx * TN];
            float bv[TN] = {b4.x, b4.y, b4.z, b4.w};
#pragma unroll
            for (int i = 0; i < TM; i++)
#pragma unroll
                for (int j = 0; j < TN; j++)
                    acc[i][j] = fmaf(a[i], bv[j], acc[i][j]);
        }
        __syncthreads();
    }

    // BN epilogue + store
#pragma unroll
    for (int i = 0; i < TM; i++) {
        int r = row0 + ty * TM + i;
        float s  = gg[r] * rsqrtf(vv[r] + EPS);
        float sh = bb[r] - mm[r] * s;
#pragma unroll
        for (int j = 0; j < TN; j++) {
            float val = acc[i][j] * s + sh;
            int col = col0 + tx * TN + j;
            if (scatter == 0) {
                C[r * N + col] = val;
            } else {
                int bimg = col / NSP;
                int sp   = col - bimg * NSP;
                C[bimg * (DIM * NSP) + r * NSP + sp] = val;
            }
        }
    }
}

// ---------------------------------------------------------------------------
// K2: depthwise 3x3 conv on q (first 256 rows of qkv) + BN
// ---------------------------------------------------------------------------
__global__ void k_dwconv_bn(const float* __restrict__ qkv,
                            const float* __restrict__ w,
                            float* __restrict__ qout,
                            const float* __restrict__ gg, const float* __restrict__ bb,
                            const float* __restrict__ mm, const float* __restrict__ vv)
{
    int i = blockIdx.x * 256 + threadIdx.x;
    if (i >= NH_KD * NTOT) return;
    int sp = i % NSP;
    int b  = (i / NSP) % BATCH;
    int c  = i / NTOT;
    int y = sp / RES, x = sp % RES;

    const float* base = qkv + c * NTOT + b * NSP;
    const float* wc = w + c * 9;
    float acc = 0.f;
#pragma unroll
    for (int dy = -1; dy <= 1; dy++) {
        int yy = y + dy;
        if (yy < 0 || yy >= RES) continue;
#pragma unroll
        for (int dx = -1; dx <= 1; dx++) {
            int xx = x + dx;
            if (xx < 0 || xx >= RES) continue;
            acc = fmaf(wc[(dy + 1) * 3 + (dx + 1)], base[yy * RES + xx], acc);
        }
    }
    float s  = gg[c] * rsqrtf(vv[c] + EPS);
    float sh = bb[c] - mm[c] * s;
    qout[i] = acc * s + sh;
}

// ---------------------------------------------------------------------------
// K3: fused attention per (b,h): softmax(q^T k * scale + bias) @ v^T, + ReLU
//   smem: q[32][197], k[32][197], v[128][197], p[8][196], bias[196]
// ---------------------------------------------------------------------------
#define PADN 197
#define ATTN_SMEM ((2 * KEY_DIM * PADN + DV * PADN + 8 * NSP + NSP) * 4)

__global__ __launch_bounds__(256) void k_attn(
    const float* __restrict__ qbuf, const float* __restrict__ qkv,
    const float* __restrict__ biases, const int* __restrict__ idxs,
    float* __restrict__ obuf)
{
    extern __shared__ float sm[];
    float* q_s = sm;
    float* k_s = q_s + KEY_DIM * PADN;
    float* v_s = k_s + KEY_DIM * PADN;
    float* p_s = v_s + DV * PADN;
    float* b_s = p_s + 8 * NSP;

    const int bh = blockIdx.x;
    const int b = bh >> 3;
    const int h = bh & 7;
    const int tid = threadIdx.x;

    for (int i = tid; i < KEY_DIM * NSP; i += 256) {
        int d = i / NSP, m = i % NSP;
        q_s[d * PADN + m] = qbuf[(h * KEY_DIM + d) * NTOT + b * NSP + m];
        k_s[d * PADN + m] = qkv [(NH_KD + h * KEY_DIM + d) * NTOT + b * NSP + m];
    }
    for (int i = tid; i < DV * NSP; i += 256) {
        int d = i / NSP, m = i % NSP;
        v_s[d * PADN + m] = qkv[(2 * NH_KD + h * DV + d) * NTOT + b * NSP + m];
    }
    if (tid < NSP) b_s[tid] = biases[h * NSP + tid];
    __syncthreads();

    const int warp = tid >> 5, lane = tid & 31;
    const float scale = 0.17677669529663687f;  // 1/sqrt(32)

    for (int n = warp; n < NSP; n += 8) {
        float acc[7];
#pragma unroll
        for (int j = 0; j < 7; j++) acc[j] = 0.f;
#pragma unroll 4
        for (int d = 0; d < KEY_DIM; d++) {
            float qv = q_s[d * PADN + n];
#pragma unroll
            for (int j = 0; j < 7; j++)
                acc[j] = fmaf(qv, k_s[d * PADN + lane + 32 * j], acc[j]);
        }
        float mx = -1e30f;
#pragma unroll
        for (int j = 0; j < 7; j++) {
            int m = lane + 32 * j;
            if (m < NSP) {
                acc[j] = acc[j] * scale + b_s[__ldg(&idxs[n * NSP + m])];
                mx = fmaxf(mx, acc[j]);
            } else acc[j] = -1e30f;
        }
#pragma unroll
        for (int off = 16; off; off >>= 1)
            mx = fmaxf(mx, __shfl_xor_sync(0xFFFFFFFFu, mx, off));
        float sum = 0.f;
#pragma unroll
        for (int j = 0; j < 7; j++) {
            float e = (lane + 32 * j < NSP) ? __expf(acc[j] - mx) : 0.f;
            acc[j] = e;
            sum += e;
        }
#pragma unroll
        for (int off = 16; off; off >>= 1)
            sum += __shfl_xor_sync(0xFFFFFFFFu, sum, off);
        float inv = 1.f / sum;

        __syncwarp();
#pragma unroll
        for (int j = 0; j < 7; j++) {
            int m = lane + 32 * j;
            if (m < NSP) p_s[warp * NSP + m] = acc[j] * inv;
        }
        __syncwarp();

        // out[d, n] = sum_m p[m] * v[d, m], each lane owns d = lane + 32t
        float o0 = 0.f, o1 = 0.f, o2 = 0.f, o3 = 0.f;
        const float* pr = &p_s[warp * NSP];
        const float* v0 = &v_s[(lane      ) * PADN];
        const float* v1 = &v_s[(lane + 32 ) * PADN];
        const float* v2 = &v_s[(lane + 64 ) * PADN];
        const float* v3 = &v_s[(lane + 96 ) * PADN];
#pragma unroll 4
        for (int m = 0; m < NSP; m++) {
            float pv = pr[m];
            o0 = fmaf(pv, v0[m], o0);
            o1 = fmaf(pv, v1[m], o1);
            o2 = fmaf(pv, v2[m], o2);
            o3 = fmaf(pv, v3[m], o3);
        }
        int base = (h * DV) * NTOT + b * NSP + n;
        obuf[base + (lane      ) * NTOT] = fmaxf(o0, 0.f);
        obuf[base + (lane + 32 ) * NTOT] = fmaxf(o1, 0.f);
        obuf[base + (lane + 64 ) * NTOT] = fmaxf(o2, 0.f);
        obuf[base + (lane + 96 ) * NTOT] = fmaxf(o3, 0.f);
        __syncwarp();
    }
}

// ---------------------------------------------------------------------------
// launch
// ---------------------------------------------------------------------------
extern "C" void kernel_launch(void* const* d_in, const int* in_sizes, int n_in,
                              void* d_out, int out_size)
{
    const float* x      = (const float*)d_in[0];
    const float* qkv_w  = (const float*)d_in[1];
    const float* qkv_g  = (const float*)d_in[2];
    const float* qkv_b  = (const float*)d_in[3];
    const float* qkv_m  = (const float*)d_in[4];
    const float* qkv_v  = (const float*)d_in[5];
    const float* dw_w   = (const float*)d_in[6];
    const float* dw_g   = (const float*)d_in[7];
    const float* dw_b   = (const float*)d_in[8];
    const float* dw_m   = (const float*)d_in[9];
    const float* dw_v   = (const float*)d_in[10];
    const float* proj_w = (const float*)d_in[11];
    const float* proj_g = (const float*)d_in[12];
    const float* proj_b = (const float*)d_in[13];
    const float* proj_m = (const float*)d_in[14];
    const float* proj_v = (const float*)d_in[15];
    const float* ab     = (const float*)d_in[16];
    const int*   idxs   = (const int*)  d_in[17];
    float* out = (float*)d_out;

    float *xT, *qkvb, *qb, *ob;
    cudaGetSymbolAddress((void**)&xT,   g_xT);
    cudaGetSymbolAddress((void**)&qkvb, g_qkv);
    cudaGetSymbolAddress((void**)&qb,   g_q);
    cudaGetSymbolAddress((void**)&ob,   g_o);

    cudaFuncSetAttribute(k_attn, cudaFuncAttributeMaxDynamicSharedMemorySize, ATTN_SMEM);

    // K0: transpose
    k_transpose<<<(DIM * NTOT + 255) / 256, 256>>>(x, xT);

    // K1: qkv GEMM + BN  (M=1536, N=50176, K=384)
    {
        dim3 grid(NTOT / BN, H_QKV / BM);
        k_gemm_bn<<<grid, 256>>>(qkv_w, xT, qkvb, H_QKV, NTOT, DIM,
                                 qkv_g, qkv_b, qkv_m, qkv_v, 0);
    }

    // K2: depthwise conv + BN
    k_dwconv_bn<<<(NH_KD * NTOT + 255) / 256, 256>>>(qkvb, dw_w, qb,
                                                     dw_g, dw_b, dw_m, dw_v);

    // K3: attention (+ ReLU)
    k_attn<<<BATCH * HEADS, 256, ATTN_SMEM>>>(qb, qkvb, ab, idxs, ob);

    // K4: proj GEMM + BN, scatter-store into [B, 384, 14, 14]
    {
        dim3 grid(NTOT / BN, DIM / BM);
        k_gemm_bn<<<grid, 256>>>(proj_w, ob, out, DIM, NTOT, DH,
                                 proj_g, proj_b, proj_m, proj_v, 1);
    }
}

// round 2
// speedup vs baseline: 1.7944x; 1.7944x over previous
#include <cuda_runtime.h>
#include <math.h>
#include <stdint.h>

// ---------------------------------------------------------------------------
// Problem constants
// ---------------------------------------------------------------------------
#define BATCH   256
#define DIM     384
#define KEY_DIM 32
#define HEADS   8
#define RES     14
#define NSP     196            // RES*RES
#define NH_KD   256            // KEY_DIM*HEADS
#define DV      128            // RATIO*KEY_DIM
#define DH      1024           // DV*HEADS
#define H_QKV   1536           // DH + 2*NH_KD
#define NTOT    (BATCH*NSP)    // 50176
#define EPS     1e-5f

// ---------------------------------------------------------------------------
// Scratch (device globals; allocation-free per harness rules)
// ---------------------------------------------------------------------------
__device__ float g_xT [DIM   * NTOT];   //  77 MB : x transposed  [384, 50176]
__device__ float g_qkv[H_QKV * NTOT];   // 308 MB : qkv (BN'd)    [1536, 50176]
__device__ float g_q  [NH_KD * NTOT];   //  51 MB : q after dwconv+BN
__device__ float g_o  [DH    * NTOT];   // 205 MB : relu(attn out) [1024, 50176]

// ---------------------------------------------------------------------------
// K0: transpose x [B,384,196] -> xT [384, B*196]
// ---------------------------------------------------------------------------
__global__ void k_transpose(const float* __restrict__ x, float* __restrict__ xT) {
    int i = blockIdx.x * 256 + threadIdx.x;
    if (i >= DIM * NTOT) return;
    int n = i % NSP;
    int c = (i / NSP) % DIM;
    int b = i / (NSP * DIM);
    xT[c * NTOT + b * NSP + n] = x[i];
}

// ---------------------------------------------------------------------------
// TF32 tensor-core GEMM with fused BN epilogue.
//   C[M,N] = BN( A[M,K] * B[K,N] ),  A row-major (weights), B row-major (data)
//   Block 128x128, BK=32, 8 warps (2 along M x 4 along N), warp tile 64x32.
//   mma.sync.aligned.m16n8k8.row.col.f32.tf32.tf32.f32
// ---------------------------------------------------------------------------
#define GBM 128
#define GBN 128
#define GBK 32

__device__ __forceinline__ uint32_t f2tf32(float x) {
    uint32_t u;
    asm("cvt.rna.tf32.f32 %0, %1;" : "=r"(u) : "f"(x));
    return u;
}

__global__ __launch_bounds__(256) void k_gemm_tf32(
    const float* __restrict__ A, const float* __restrict__ B,
    float* __restrict__ C, int M, int N, int K,
    const float* __restrict__ gg, const float* __restrict__ bb,
    const float* __restrict__ mm, const float* __restrict__ vv,
    int scatter)
{
    __shared__ uint32_t As[GBM][GBK + 4];   // [m][k], stride 36 -> conflict-free
    __shared__ uint32_t Bs[GBK][GBN + 8];   // [k][n], stride 136 -> conflict-free

    const int tid  = threadIdx.x;
    const int lane = tid & 31;
    const int wid  = tid >> 5;
    const int wm   = wid & 1;      // 0..1 : 64-row slice
    const int wn   = wid >> 1;     // 0..3 : 32-col slice
    const int row0 = blockIdx.x * GBM;   // M fastest -> weight stays hot in L2
    const int col0 = blockIdx.y * GBN;
    const int grp  = lane >> 2;    // 0..7
    const int tig  = lane & 3;     // 0..3

    float acc[4][4][4];
#pragma unroll
    for (int a = 0; a < 4; a++)
#pragma unroll
        for (int b = 0; b < 4; b++)
#pragma unroll
            for (int c = 0; c < 4; c++) acc[a][b][c] = 0.f;

    for (int k0 = 0; k0 < K; k0 += GBK) {
        // ---- load A tile 128x32 (1024 float4 slots) ----
#pragma unroll
        for (int i = 0; i < 4; i++) {
            int s  = tid + i * 256;
            int r  = s >> 3;            // 0..127
            int kq = s & 7;             // float4 index within 32
            float4 f = *(const float4*)&A[(size_t)(row0 + r) * K + k0 + kq * 4];
            uint4 t;
            t.x = f2tf32(f.x); t.y = f2tf32(f.y);
            t.z = f2tf32(f.z); t.w = f2tf32(f.w);
            *(uint4*)&As[r][kq * 4] = t;
        }
        // ---- load B tile 32x128 (1024 float4 slots) ----
#pragma unroll
        for (int i = 0; i < 4; i++) {
            int s  = tid + i * 256;
            int kr = s >> 5;            // 0..31
            int nq = s & 31;
            float4 f = *(const float4*)&B[(size_t)(k0 + kr) * N + col0 + nq * 4];
            uint4 t;
            t.x = f2tf32(f.x); t.y = f2tf32(f.y);
            t.z = f2tf32(f.z); t.w = f2tf32(f.w);
            *(uint4*)&Bs[kr][nq * 4] = t;
        }
        __syncthreads();

#pragma unroll
        for (int ks = 0; ks < 4; ks++) {
            const int kb = ks * 8;
            uint32_t af[4][4], bf[4][2];
#pragma unroll
            for (int mf = 0; mf < 4; mf++) {
                int r = wm * 64 + mf * 16 + grp;
                af[mf][0] = As[r    ][kb + tig];
                af[mf][1] = As[r + 8][kb + tig];
                af[mf][2] = As[r    ][kb + tig + 4];
                af[mf][3] = As[r + 8][kb + tig + 4];
            }
#pragma unroll
            for (int nf = 0; nf < 4; nf++) {
                int c = wn * 32 + nf * 8 + grp;
                bf[nf][0] = Bs[kb + tig    ][c];
                bf[nf][1] = Bs[kb + tig + 4][c];
            }
#pragma unroll
            for (int mf = 0; mf < 4; mf++)
#pragma unroll
                for (int nf = 0; nf < 4; nf++) {
                    asm volatile(
                        "mma.sync.aligned.m16n8k8.row.col.f32.tf32.tf32.f32 "
                        "{%0,%1,%2,%3}, {%4,%5,%6,%7}, {%8,%9}, {%0,%1,%2,%3};"
                        : "+f"(acc[mf][nf][0]), "+f"(acc[mf][nf][1]),
                          "+f"(acc[mf][nf][2]), "+f"(acc[mf][nf][3])
                        : "r"(af[mf][0]), "r"(af[mf][1]), "r"(af[mf][2]), "r"(af[mf][3]),
                          "r"(bf[nf][0]), "r"(bf[nf][1]));
                }
        }
        __syncthreads();
    }

    // ---- BN epilogue + store ----
#pragma unroll
    for (int mf = 0; mf < 4; mf++) {
        int r0 = row0 + wm * 64 + mf * 16 + grp;
        int r1 = r0 + 8;
        float s0 = gg[r0] * rsqrtf(vv[r0] + EPS);
        float h0 = bb[r0] - mm[r0] * s0;
        float s1 = gg[r1] * rsqrtf(vv[r1] + EPS);
        float h1 = bb[r1] - mm[r1] * s1;
#pragma unroll
        for (int nf = 0; nf < 4; nf++) {
            int cc = col0 + wn * 32 + nf * 8 + tig * 2;
            float v00 = acc[mf][nf][0] * s0 + h0;
            float v01 = acc[mf][nf][1] * s0 + h0;
            float v10 = acc[mf][nf][2] * s1 + h1;
            float v11 = acc[mf][nf][3] * s1 + h1;
            if (scatter == 0) {
                float2 p0 = make_float2(v00, v01);
                float2 p1 = make_float2(v10, v11);
                *(float2*)&C[(size_t)r0 * N + cc] = p0;
                *(float2*)&C[(size_t)r1 * N + cc] = p1;
            } else {
                int b0i = cc / NSP,      sp0 = cc - b0i * NSP;
                int b1i = (cc+1) / NSP,  sp1 = (cc+1) - b1i * NSP;
                C[b0i * (DIM * NSP) + r0 * NSP + sp0] = v00;
                C[b1i * (DIM * NSP) + r0 * NSP + sp1] = v01;
                C[b0i * (DIM * NSP) + r1 * NSP + sp0] = v10;
                C[b1i * (DIM * NSP) + r1 * NSP + sp1] = v11;
            }
        }
    }
}

// ---------------------------------------------------------------------------
// K2: depthwise 3x3 conv on q (first 256 rows of qkv) + BN
// ---------------------------------------------------------------------------
__global__ void k_dwconv_bn(const float* __restrict__ qkv,
                            const float* __restrict__ w,
                            float* __restrict__ qout,
                            const float* __restrict__ gg, const float* __restrict__ bb,
                            const float* __restrict__ mm, const float* __restrict__ vv)
{
    int i = blockIdx.x * 256 + threadIdx.x;
    if (i >= NH_KD * NTOT) return;
    int sp = i % NSP;
    int b  = (i / NSP) % BATCH;
    int c  = i / NTOT;
    int y = sp / RES, x = sp % RES;

    const float* base = qkv + c * NTOT + b * NSP;
    const float* wc = w + c * 9;
    float acc = 0.f;
#pragma unroll
    for (int dy = -1; dy <= 1; dy++) {
        int yy = y + dy;
        if (yy < 0 || yy >= RES) continue;
#pragma unroll
        for (int dx = -1; dx <= 1; dx++) {
            int xx = x + dx;
            if (xx < 0 || xx >= RES) continue;
            acc = fmaf(wc[(dy + 1) * 3 + (dx + 1)], base[yy * RES + xx], acc);
        }
    }
    float s  = gg[c] * rsqrtf(vv[c] + EPS);
    float sh = bb[c] - mm[c] * s;
    qout[i] = acc * s + sh;
}

// ---------------------------------------------------------------------------
// K3: fused attention per (b,h): softmax(q^T k * scale + bias) @ v^T, + ReLU
//   4 queries per warp-iteration; float4-vectorized PV (v pad 204 -> CF LDS.128)
// ---------------------------------------------------------------------------
#define QPAD 200
#define KPAD 197
#define VPAD 204
#define PPAD 200
// floats: q 32*200, k 32*197, v 128*204, p 32*200, bias 196
#define Q_OFF 0
#define K_OFF (32*QPAD)
#define V_OFF (K_OFF + 32*KPAD)
#define P_OFF (V_OFF + 128*VPAD)
#define B_OFF (P_OFF + 32*PPAD)
#define ATTN_SMEM ((B_OFF + NSP) * 4)

__global__ __launch_bounds__(256) void k_attn(
    const float* __restrict__ qbuf, const float* __restrict__ qkv,
    const float* __restrict__ biases, const int* __restrict__ idxs,
    float* __restrict__ obuf)
{
    extern __shared__ float sm[];
    float* q_s = sm + Q_OFF;
    float* k_s = sm + K_OFF;
    float* v_s = sm + V_OFF;
    float* p_s = sm + P_OFF;
    float* b_s = sm + B_OFF;

    const int bh = blockIdx.x;
    const int b = bh >> 3;
    const int h = bh & 7;
    const int tid = threadIdx.x;

    for (int i = tid; i < KEY_DIM * NSP; i += 256) {
        int d = i / NSP, m = i % NSP;
        q_s[d * QPAD + m] = qbuf[(h * KEY_DIM + d) * NTOT + b * NSP + m];
        k_s[d * KPAD + m] = qkv [(NH_KD + h * KEY_DIM + d) * NTOT + b * NSP + m];
    }
    for (int i = tid; i < DV * NSP; i += 256) {
        int d = i / NSP, m = i % NSP;
        v_s[d * VPAD + m] = qkv[(2 * NH_KD + h * DV + d) * NTOT + b * NSP + m];
    }
    if (tid < NSP) b_s[tid] = biases[h * NSP + tid];
    __syncthreads();

    const int warp = tid >> 5, lane = tid & 31;
    const float scale = 0.17677669529663687f;  // 1/sqrt(32)

    for (int g = warp; g < NSP / 4; g += 8) {
        const int n0 = g * 4;

        // ---- QK: 4 queries x 7 key-chunks ----
        float acc[4][7];
#pragma unroll
        for (int i = 0; i < 4; i++)
#pragma unroll
            for (int j = 0; j < 7; j++) acc[i][j] = 0.f;

#pragma unroll 4
        for (int d = 0; d < KEY_DIM; d++) {
            float4 q4 = *(const float4*)&q_s[d * QPAD + n0];
            const float* kr = &k_s[d * KPAD + lane];
#pragma unroll
            for (int j = 0; j < 7; j++) {
                float kv = kr[32 * j];
                acc[0][j] = fmaf(q4.x, kv, acc[0][j]);
                acc[1][j] = fmaf(q4.y, kv, acc[1][j]);
                acc[2][j] = fmaf(q4.z, kv, acc[2][j]);
                acc[3][j] = fmaf(q4.w, kv, acc[3][j]);
            }
        }

        // ---- softmax per query ----
#pragma unroll
        for (int i = 0; i < 4; i++) {
            int n = n0 + i;
            float mx = -1e30f;
#pragma unroll
            for (int j = 0; j < 7; j++) {
                int m = lane + 32 * j;
                if (m < NSP) {
                    acc[i][j] = acc[i][j] * scale + b_s[__ldg(&idxs[n * NSP + m])];
                    mx = fmaxf(mx, acc[i][j]);
                } else acc[i][j] = -1e30f;
            }
#pragma unroll
            for (int off = 16; off; off >>= 1)
                mx = fmaxf(mx, __shfl_xor_sync(0xFFFFFFFFu, mx, off));
            float sum = 0.f;
#pragma unroll
            for (int j = 0; j < 7; j++) {
                float e = (lane + 32 * j < NSP) ? __expf(acc[i][j] - mx) : 0.f;
                acc[i][j] = e;
                sum += e;
            }
#pragma unroll
            for (int off = 16; off; off >>= 1)
                sum += __shfl_xor_sync(0xFFFFFFFFu, sum, off);
            float inv = 1.f / sum;
#pragma unroll
            for (int j = 0; j < 7; j++) {
                int m = lane + 32 * j;
                if (m < NSP) p_s[(warp * 4 + i) * PPAD + m] = acc[i][j] * inv;
            }
        }
        __syncwarp();

        // ---- PV: o[4 queries][4 d-blocks], float4 over m ----
        float o[4][4];
#pragma unroll
        for (int i = 0; i < 4; i++)
#pragma unroll
            for (int d = 0; d < 4; d++) o[i][d] = 0.f;

        const float* p0r = &p_s[(warp * 4 + 0) * PPAD];
        const float* p1r = &p_s[(warp * 4 + 1) * PPAD];
        const float* p2r = &p_s[(warp * 4 + 2) * PPAD];
        const float* p3r = &p_s[(warp * 4 + 3) * PPAD];
        const float* v0r = &v_s[(lane      ) * VPAD];
        const float* v1r = &v_s[(lane + 32 ) * VPAD];
        const float* v2r = &v_s[(lane + 64 ) * VPAD];
        const float* v3r = &v_s[(lane + 96 ) * VPAD];

#pragma unroll 7
        for (int mq = 0; mq < NSP / 4; mq++) {
            int m = mq * 4;
            float4 pa = *(const float4*)&p0r[m];
            float4 pb = *(const float4*)&p1r[m];
            float4 pc = *(const float4*)&p2r[m];
            float4 pd = *(const float4*)&p3r[m];
            float4 va = *(const float4*)&v0r[m];
            float4 vb = *(const float4*)&v1r[m];
            float4 vc = *(const float4*)&v2r[m];
            float4 vd = *(const float4*)&v3r[m];
#define PV1(P, i) \
            o[i][0] = fmaf(P.x, va.x, o[i][0]); o[i][0] = fmaf(P.y, va.y, o[i][0]); \
            o[i][0] = fmaf(P.z, va.z, o[i][0]); o[i][0] = fmaf(P.w, va.w, o[i][0]); \
            o[i][1] = fmaf(P.x, vb.x, o[i][1]); o[i][1] = fmaf(P.y, vb.y, o[i][1]); \
            o[i][1] = fmaf(P.z, vb.z, o[i][1]); o[i][1] = fmaf(P.w, vb.w, o[i][1]); \
            o[i][2] = fmaf(P.x, vc.x, o[i][2]); o[i][2] = fmaf(P.y, vc.y, o[i][2]); \
            o[i][2] = fmaf(P.z, vc.z, o[i][2]); o[i][2] = fmaf(P.w, vc.w, o[i][2]); \
            o[i][3] = fmaf(P.x, vd.x, o[i][3]); o[i][3] = fmaf(P.y, vd.y, o[i][3]); \
            o[i][3] = fmaf(P.z, vd.z, o[i][3]); o[i][3] = fmaf(P.w, vd.w, o[i][3]);
            PV1(pa, 0) PV1(pb, 1) PV1(pc, 2) PV1(pd, 3)
#undef PV1
        }

        // ---- store with ReLU ----
        int base = (h * DV) * NTOT + b * NSP + n0;
#pragma unroll
        for (int db = 0; db < 4; db++) {
            int rowoff = (lane + 32 * db) * NTOT;
#pragma unroll
            for (int i = 0; i < 4; i++)
                obuf[base + rowoff + i] = fmaxf(o[i][db], 0.f);
        }
        __syncwarp();
    }
}

// ---------------------------------------------------------------------------
// launch
// ---------------------------------------------------------------------------
extern "C" void kernel_launch(void* const* d_in, const int* in_sizes, int n_in,
                              void* d_out, int out_size)
{
    const float* x      = (const float*)d_in[0];
    const float* qkv_w  = (const float*)d_in[1];
    const float* qkv_g  = (const float*)d_in[2];
    const float* qkv_b  = (const float*)d_in[3];
    const float* qkv_m  = (const float*)d_in[4];
    const float* qkv_v  = (const float*)d_in[5];
    const float* dw_w   = (const float*)d_in[6];
    const float* dw_g   = (const float*)d_in[7];
    const float* dw_b   = (const float*)d_in[8];
    const float* dw_m   = (const float*)d_in[9];
    const float* dw_v   = (const float*)d_in[10];
    const float* proj_w = (const float*)d_in[11];
    const float* proj_g = (const float*)d_in[12];
    const float* proj_b = (const float*)d_in[13];
    const float* proj_m = (const float*)d_in[14];
    const float* proj_v = (const float*)d_in[15];
    const float* ab     = (const float*)d_in[16];
    const int*   idxs   = (const int*)  d_in[17];
    float* out = (float*)d_out;

    float *xT, *qkvb, *qb, *ob;
    cudaGetSymbolAddress((void**)&xT,   g_xT);
    cudaGetSymbolAddress((void**)&qkvb, g_qkv);
    cudaGetSymbolAddress((void**)&qb,   g_q);
    cudaGetSymbolAddress((void**)&ob,   g_o);

    cudaFuncSetAttribute(k_attn, cudaFuncAttributeMaxDynamicSharedMemorySize, ATTN_SMEM);

    // K0: transpose
    k_transpose<<<(DIM * NTOT + 255) / 256, 256>>>(x, xT);

    // K1: qkv GEMM + BN  (M=1536, N=50176, K=384)  [M fastest for L2 reuse]
    {
        dim3 grid(H_QKV / GBM, NTOT / GBN);
        k_gemm_tf32<<<grid, 256>>>(qkv_w, xT, qkvb, H_QKV, NTOT, DIM,
                                   qkv_g, qkv_b, qkv_m, qkv_v, 0);
    }

    // K2: depthwise conv + BN
    k_dwconv_bn<<<(NH_KD * NTOT + 255) / 256, 256>>>(qkvb, dw_w, qb,
                                                     dw_g, dw_b, dw_m, dw_v);

    // K3: attention (+ ReLU)
    k_attn<<<BATCH * HEADS, 256, ATTN_SMEM>>>(qb, qkvb, ab, idxs, ob);

    // K4: proj GEMM + BN, scatter-store into [B, 384, 14, 14]
    {
        dim3 grid(DIM / GBM, NTOT / GBN);
        k_gemm_tf32<<<grid, 256>>>(proj_w, ob, out, DIM, NTOT, DH,
                                   proj_g, proj_b, proj_m, proj_v, 1);
    }
}